// round 9
// baseline (speedup 1.0000x reference)
#include <cuda_runtime.h>
#include <cstdint>

#define BSZ  4
#define NN   2048
#define NH   2
#define FIN  768
#define FOUT 768
#define NEG_SLOPE 0.2f

#define NEG_INF (__int_as_float(0xff800000))

// ---------------- scratch (allocation-free: __device__ globals) ----------------
__device__ float g_hprime[(size_t)NH * BSZ * NN * FOUT];   // [hd][b][n][o]  ~50 MB
__device__ float g_attn[(size_t)NH * BSZ * NN * NN];       // [hd][b][i][j] ~134 MB
__device__ float g_src[NH * BSZ * NN];
__device__ float g_dst[NH * BSZ * NN];
__device__ int   g_adjmode;                                // 0=int32, 1=float32, 2=byte

// ---------------- adj dtype detection ----------------
// Scan the first 1M uint32 words (4MB — safe under every dtype interpretation,
// since the smallest possible buffer is 16.7MB of bytes). adj values are 0/1.
//   int32 buffer  -> every word is 0 or 1
//   float32 buffer-> every word is 0 or 0x3f800000
//   byte buffer   -> words are 4 packed 0/1 bytes (most words >1, not float pattern)
__global__ void adj_detect_kernel(const uint32_t* __restrict__ adj_words)
{
    __shared__ int s_not01, s_notf;
    if (threadIdx.x == 0) { s_not01 = 0; s_notf = 0; }
    __syncthreads();

    int not01 = 0, notf = 0;
    const int NWORDS = 1 << 20;
    for (int i = threadIdx.x; i < NWORDS; i += blockDim.x) {
        uint32_t v = adj_words[i];
        if (v > 1u) not01 = 1;
        if (v != 0u && v != 0x3f800000u) notf = 1;
    }
    if (not01) atomicOr(&s_not01, 1);
    if (notf)  atomicOr(&s_notf, 1);
    __syncthreads();
    if (threadIdx.x == 0) {
        int mode;
        if (!s_not01)      mode = 0;   // int32 (or bool widened to 0/1 ints)
        else if (!s_notf)  mode = 1;   // float32
        else               mode = 2;   // packed bytes
        g_adjmode = mode;
    }
}

// ---------------- 128x128x8 SGEMM, 256 threads, 8x8 microtile ----------------
template <bool ADD_BIAS>
__device__ __forceinline__ void sgemm128(
    const float* __restrict__ A, const float* __restrict__ B,
    float* __restrict__ C, const float* __restrict__ bias,
    int M, int Nn, int K)
{
    __shared__ float As[8][128];
    __shared__ float Bs[8][128];

    const int tid = threadIdx.x;
    const int bm = blockIdx.y * 128;
    const int bn = blockIdx.x * 128;

    const int a_row = tid >> 1;            // 0..127
    const int a_col = (tid & 1) << 2;      // 0 or 4
    const int b_row = tid >> 5;            // 0..7
    const int b_col = (tid & 31) << 2;     // 0..124

    const int ty = tid >> 4;               // 0..15
    const int tx = tid & 15;               // 0..15

    const float* Ap = A + (size_t)(bm + a_row) * K + a_col;
    const float* Bp = B + (size_t)b_row * Nn + bn + b_col;

    float4 a_pf = *(const float4*)Ap;
    float4 b_pf = *(const float4*)Bp;

    float acc[8][8];
    #pragma unroll
    for (int i = 0; i < 8; i++)
        #pragma unroll
        for (int j = 0; j < 8; j++) acc[i][j] = 0.f;

    const int ktiles = K >> 3;
    for (int t = 0; t < ktiles; t++) {
        As[a_col + 0][a_row] = a_pf.x;
        As[a_col + 1][a_row] = a_pf.y;
        As[a_col + 2][a_row] = a_pf.z;
        As[a_col + 3][a_row] = a_pf.w;
        *(float4*)&Bs[b_row][b_col] = b_pf;
        __syncthreads();

        if (t + 1 < ktiles) {
            a_pf = *(const float4*)(Ap + (t + 1) * 8);
            b_pf = *(const float4*)(Bp + (size_t)(t + 1) * 8 * Nn);
        }

        #pragma unroll
        for (int k = 0; k < 8; k++) {
            float4 a0 = *(const float4*)&As[k][ty * 4];
            float4 a1 = *(const float4*)&As[k][64 + ty * 4];
            float4 b0 = *(const float4*)&Bs[k][tx * 4];
            float4 b1 = *(const float4*)&Bs[k][64 + tx * 4];
            float av[8] = {a0.x, a0.y, a0.z, a0.w, a1.x, a1.y, a1.z, a1.w};
            float bv[8] = {b0.x, b0.y, b0.z, b0.w, b1.x, b1.y, b1.z, b1.w};
            #pragma unroll
            for (int i = 0; i < 8; i++)
                #pragma unroll
                for (int j = 0; j < 8; j++)
                    acc[i][j] += av[i] * bv[j];
        }
        __syncthreads();
    }

    #pragma unroll
    for (int ih = 0; ih < 2; ih++) {
        #pragma unroll
        for (int ii = 0; ii < 4; ii++) {
            int row = bm + ih * 64 + ty * 4 + ii;
            float* cr = C + (size_t)row * Nn + bn;
            #pragma unroll
            for (int jh = 0; jh < 2; jh++) {
                int col = jh * 64 + tx * 4;
                float4 v;
                v.x = acc[ih * 4 + ii][jh * 4 + 0];
                v.y = acc[ih * 4 + ii][jh * 4 + 1];
                v.z = acc[ih * 4 + ii][jh * 4 + 2];
                v.w = acc[ih * 4 + ii][jh * 4 + 3];
                if (ADD_BIAS) {
                    float4 bb = *(const float4*)(bias + bn + col);
                    v.x += bb.x; v.y += bb.y; v.z += bb.z; v.w += bb.w;
                }
                *(float4*)(cr + col) = v;
            }
        }
    }
}

// GEMM1: h_prime[hd][b][n][o] = sum_f h[b][n][f] * w[hd][f][o]
__global__ __launch_bounds__(256, 2) void gemm1_kernel(
    const float* __restrict__ h, const float* __restrict__ w)
{
    int hd = blockIdx.z;
    sgemm128<false>(h,
                    w + (size_t)hd * FIN * FOUT,
                    g_hprime + (size_t)hd * BSZ * NN * FOUT,
                    nullptr, BSZ * NN, FOUT, FIN);
}

// GEMM2: out[b][hd][i][o] = sum_j attn[hd][b][i][j] * h_prime[hd][b][j][o] + bias[o]
__global__ __launch_bounds__(256, 2) void gemm2_kernel(
    const float* __restrict__ bias, float* __restrict__ out)
{
    int z = blockIdx.z;            // z = hd*BSZ + b
    int hd = z / BSZ;
    int b  = z % BSZ;
    sgemm128<true>(g_attn + (size_t)z * NN * NN,
                   g_hprime + (size_t)z * NN * FOUT,
                   out + (size_t)(b * NH + hd) * NN * FOUT,
                   bias, NN, FOUT, NN);
}

// ---------------- attn_src / attn_dst: one warp per (hd,b,n) row ----------------
__global__ __launch_bounds__(256) void attvec_kernel(
    const float* __restrict__ a_src, const float* __restrict__ a_dst)
{
    int warp = (blockIdx.x * blockDim.x + threadIdx.x) >> 5;
    int lane = threadIdx.x & 31;
    if (warp >= NH * BSZ * NN) return;
    int hd = warp / (BSZ * NN);

    const float* hp = g_hprime + (size_t)warp * FOUT;
    const float* as = a_src + hd * FOUT;   // a_src is [H, F_OUT, 1] contiguous
    const float* ad = a_dst + hd * FOUT;

    float s1 = 0.f, s2 = 0.f;
    for (int o = lane * 4; o < FOUT; o += 32 * 4) {
        float4 v = *(const float4*)(hp + o);
        float4 x = *(const float4*)(as + o);
        float4 y = *(const float4*)(ad + o);
        float t0 = tanhf(v.x), t1 = tanhf(v.y), t2 = tanhf(v.z), t3 = tanhf(v.w);
        s1 += t0 * x.x + t1 * x.y + t2 * x.z + t3 * x.w;
        s2 += t0 * y.x + t1 * y.y + t2 * y.z + t3 * y.w;
    }
    #pragma unroll
    for (int off = 16; off; off >>= 1) {
        s1 += __shfl_xor_sync(0xffffffffu, s1, off);
        s2 += __shfl_xor_sync(0xffffffffu, s2, off);
    }
    if (lane == 0) { g_src[warp] = s1; g_dst[warp] = s2; }
}

// ---------------- masked softmax: one block per (hd,b,i) row ----------------
__global__ __launch_bounds__(256) void softmax_kernel(const void* __restrict__ adj)
{
    __shared__ float sdst[NN];
    __shared__ float sval[NN];
    __shared__ float redm[8];
    __shared__ float reds[8];
    __shared__ float bcast[2];

    const int z = blockIdx.y;               // hd*BSZ + b
    const int i = blockIdx.x;
    const int b = z & (BSZ - 1);
    const int tid  = threadIdx.x;
    const int lane = tid & 31;
    const int wid  = tid >> 5;

    const float* dstrow = g_dst + (size_t)z * NN;
    for (int j = tid * 4; j < NN; j += 256 * 4)
        *(float4*)&sdst[j] = *(const float4*)&dstrow[j];
    __syncthreads();

    const float srcv = g_src[(size_t)z * NN + i];
    const size_t rowbase = ((size_t)b * NN + i) * NN;
    const int j0 = tid * 8;                 // 256*8 == 2048: one chunk per thread

    // ---- load 8 mask bits per thread, dtype-adaptive ----
    uint32_t keep8 = 0;                     // bit u = adjacency nonzero at j0+u
    const int mode = g_adjmode;
    if (mode == 0) {                        // int32
        const int* arow = (const int*)adj + rowbase;
        int4 w0 = *(const int4*)(arow + j0);
        int4 w1 = *(const int4*)(arow + j0 + 4);
        keep8 = (w0.x != 0) | ((w0.y != 0) << 1) | ((w0.z != 0) << 2) | ((w0.w != 0) << 3)
              | ((w1.x != 0) << 4) | ((w1.y != 0) << 5) | ((w1.z != 0) << 6) | ((w1.w != 0) << 7);
    } else if (mode == 1) {                 // float32
        const float* arow = (const float*)adj + rowbase;
        float4 w0 = *(const float4*)(arow + j0);
        float4 w1 = *(const float4*)(arow + j0 + 4);
        keep8 = (w0.x != 0.f) | ((w0.y != 0.f) << 1) | ((w0.z != 0.f) << 2) | ((w0.w != 0.f) << 3)
              | ((w1.x != 0.f) << 4) | ((w1.y != 0.f) << 5) | ((w1.z != 0.f) << 6) | ((w1.w != 0.f) << 7);
    } else {                                // packed bytes (bool)
        const uint8_t* arow = (const uint8_t*)adj + rowbase;
        uint2 mraw = *(const uint2*)(arow + j0);
        #pragma unroll
        for (int u = 0; u < 4; u++) {
            keep8 |= (((mraw.x >> (8 * u)) & 0xffu) != 0u) << u;
            keep8 |= (((mraw.y >> (8 * u)) & 0xffu) != 0u) << (u + 4);
        }
    }

    float mx = NEG_INF;
    #pragma unroll
    for (int u = 0; u < 8; u++) {
        int j = j0 + u;
        bool keep = ((keep8 >> u) & 1u) || (j == i);
        float s = srcv + sdst[j];
        s = (s >= 0.f) ? s : NEG_SLOPE * s;
        float v = keep ? s : NEG_INF;
        sval[j] = v;
        mx = fmaxf(mx, v);
    }

    #pragma unroll
    for (int off = 16; off; off >>= 1) mx = fmaxf(mx, __shfl_xor_sync(0xffffffffu, mx, off));
    if (lane == 0) redm[wid] = mx;
    __syncthreads();
    if (tid < 8) {
        float x = redm[tid];
        #pragma unroll
        for (int off = 4; off; off >>= 1) x = fmaxf(x, __shfl_xor_sync(0xffu, x, off));
        if (tid == 0) bcast[0] = x;
    }
    __syncthreads();
    const float smax = bcast[0];

    float lsum = 0.f;
    #pragma unroll
    for (int u = 0; u < 8; u++) {
        int j = j0 + u;
        float v = sval[j];
        float e = (v == NEG_INF) ? 0.f : __expf(v - smax);
        sval[j] = e;
        lsum += e;
    }
    #pragma unroll
    for (int off = 16; off; off >>= 1) lsum += __shfl_xor_sync(0xffffffffu, lsum, off);
    if (lane == 0) reds[wid] = lsum;
    __syncthreads();
    if (tid < 8) {
        float x = reds[tid];
        #pragma unroll
        for (int off = 4; off; off >>= 1) x += __shfl_xor_sync(0xffu, x, off);
        if (tid == 0) bcast[1] = 1.f / x;
    }
    __syncthreads();
    const float inv = bcast[1];

    float* outrow = g_attn + ((size_t)z * NN + i) * NN;
    #pragma unroll
    for (int u = 0; u < 8; u += 4) {
        float4 v = *(const float4*)&sval[j0 + u];
        v.x *= inv; v.y *= inv; v.z *= inv; v.w *= inv;
        *(float4*)(outrow + j0 + u) = v;
    }
}

// ---------------- launch ----------------
extern "C" void kernel_launch(void* const* d_in, const int* in_sizes, int n_in,
                              void* d_out, int out_size)
{
    // Identify inputs by element count (robust to metadata ordering).
    const float *h = nullptr, *w = nullptr, *a_src = nullptr, *a_dst = nullptr, *bias = nullptr;
    const void  *adj = nullptr;
    for (int k = 0; k < n_in; k++) {
        switch (in_sizes[k]) {
            case BSZ * NN * FIN:        h    = (const float*)d_in[k]; break;   // 6291456
            case BSZ * NN * NN:         adj  = d_in[k];               break;   // 16777216
            case NH * FIN * FOUT:       w    = (const float*)d_in[k]; break;   // 1179648
            case NH * FOUT:             if (!a_src) a_src = (const float*)d_in[k];
                                        else        a_dst = (const float*)d_in[k]; break; // 1536
            case FOUT:                  bias = (const float*)d_in[k]; break;   // 768
            default: break;
        }
    }
    float* out = (float*)d_out;

    adj_detect_kernel<<<1, 256>>>((const uint32_t*)adj);

    dim3 g1(FOUT / 128, (BSZ * NN) / 128, NH);        // (6, 64, 2)
    gemm1_kernel<<<g1, 256>>>(h, w);

    attvec_kernel<<<(NH * BSZ * NN) / 8, 256>>>(a_src, a_dst);  // 8 warps/block

    dim3 g3(NN, NH * BSZ);                            // (2048, 8)
    softmax_kernel<<<g3, 256>>>(adj);

    dim3 g2(FOUT / 128, NN / 128, NH * BSZ);          // (6, 16, 8)
    gemm2_kernel<<<g2, 256>>>(bias, out);
}

// round 15
// speedup vs baseline: 1.6424x; 1.6424x over previous
#include <cuda_runtime.h>
#include <cstdint>

#define BSZ  4
#define NN   2048
#define NH   2
#define FIN  768
#define FOUT 768
#define NEG_SLOPE 0.2f
#define NEG_INF (__int_as_float(0xff800000))

// ---------------- scratch (allocation-free: __device__ globals) ----------------
__device__ float g_hpT[(size_t)NH * BSZ * FOUT * NN];   // [z][o][n]  transposed h_prime, ~50MB
__device__ float g_attn[(size_t)NH * BSZ * NN * NN];    // [z][i][j]  ~134MB
__device__ float g_wT[(size_t)NH * FOUT * FIN];         // [hd][o][f]
__device__ float g_src[NH * BSZ * NN];
__device__ float g_dst[NH * BSZ * NN];
__device__ int   g_adjmode;

// ---------------- tf32 helpers (portable sm_80+ PTX; no tcgen05) ----------------
__device__ __forceinline__ float f2tf_f(float x) {   // fp32 -> tf32 (RN), bits kept in a float reg
    uint32_t r;
    asm("cvt.rna.tf32.f32 %0, %1;" : "=r"(r) : "f"(x));
    return __uint_as_float(r);
}

__device__ __forceinline__ void mma_tf32(float* c, uint32_t a0, uint32_t a1,
                                         uint32_t a2, uint32_t a3,
                                         uint32_t b0, uint32_t b1) {
    asm volatile(
        "mma.sync.aligned.m16n8k8.row.col.f32.tf32.tf32.f32 "
        "{%0,%1,%2,%3}, {%4,%5,%6,%7}, {%8,%9}, {%0,%1,%2,%3};"
        : "+f"(c[0]), "+f"(c[1]), "+f"(c[2]), "+f"(c[3])
        : "r"(a0), "r"(a1), "r"(a2), "r"(a3), "r"(b0), "r"(b1));
}

// SMEM layout per buffer: A [128][20] (2560 floats) then B [128][20] (2560 floats).
// Buffer stride = 5120 floats; two buffers = 10240 floats = 40960 B (static SMEM).
// Stride 20 makes the (lane>>2, lane&3) fragment-load pattern conflict-free.
#define SB_STRIDE 20
#define BUF_FLTS  5120

// ---------------- mainloop: acc[4][4][4] += A[128,K] * B[128,K]^T (tf32 mma) ----------------
// A, B pre-offset to the 128-row tile origin; K-major; K = ST*16.
template <int ST>
__device__ __forceinline__ void mm_mainloop(
    const float* __restrict__ A, int lda,
    const float* __restrict__ B, int ldb,
    float* sb, float acc[4][4][4])
{
    const int tid  = threadIdx.x;
    const int lane = tid & 31;
    const int wid  = tid >> 5;
    const int wm   = (wid >> 2) * 64;     // warp M origin (0 or 64)
    const int wn   = (wid & 3) * 32;      // warp N origin (0,32,64,96)
    const int t4   = lane >> 2;           // 0..7
    const int tk   = lane & 3;            // 0..3

    // global-load mapping: idx in [0,512): row = idx>>2 (0..127 via r and r+64), col = (idx&3)*4
    const int r = tid >> 2;               // 0..63
    const int g = (tid & 3) * 4;          // 0,4,8,12

    const float* Ap0 = A + (size_t)r * lda + g;
    const float* Ap1 = A + (size_t)(r + 64) * lda + g;
    const float* Bp0 = B + (size_t)r * ldb + g;
    const float* Bp1 = B + (size_t)(r + 64) * ldb + g;

    // prologue: stage 0 -> buffer 0
    {
        float4 a0 = *(const float4*)Ap0, a1 = *(const float4*)Ap1;
        float4 b0 = *(const float4*)Bp0, b1 = *(const float4*)Bp1;
        float* As = sb;
        float* Bs = sb + 2560;
        As[r * SB_STRIDE + g + 0] = f2tf_f(a0.x); As[r * SB_STRIDE + g + 1] = f2tf_f(a0.y);
        As[r * SB_STRIDE + g + 2] = f2tf_f(a0.z); As[r * SB_STRIDE + g + 3] = f2tf_f(a0.w);
        As[(r + 64) * SB_STRIDE + g + 0] = f2tf_f(a1.x); As[(r + 64) * SB_STRIDE + g + 1] = f2tf_f(a1.y);
        As[(r + 64) * SB_STRIDE + g + 2] = f2tf_f(a1.z); As[(r + 64) * SB_STRIDE + g + 3] = f2tf_f(a1.w);
        Bs[r * SB_STRIDE + g + 0] = f2tf_f(b0.x); Bs[r * SB_STRIDE + g + 1] = f2tf_f(b0.y);
        Bs[r * SB_STRIDE + g + 2] = f2tf_f(b0.z); Bs[r * SB_STRIDE + g + 3] = f2tf_f(b0.w);
        Bs[(r + 64) * SB_STRIDE + g + 0] = f2tf_f(b1.x); Bs[(r + 64) * SB_STRIDE + g + 1] = f2tf_f(b1.y);
        Bs[(r + 64) * SB_STRIDE + g + 2] = f2tf_f(b1.z); Bs[(r + 64) * SB_STRIDE + g + 3] = f2tf_f(b1.w);
    }
    __syncthreads();

    for (int s = 0; s < ST; s++) {
        float4 na0, na1, nb0, nb1;
        if (s + 1 < ST) {
            const int k0 = (s + 1) * 16;
            na0 = *(const float4*)(Ap0 + k0);
            na1 = *(const float4*)(Ap1 + k0);
            nb0 = *(const float4*)(Bp0 + k0);
            nb1 = *(const float4*)(Bp1 + k0);
        }

        const float* Ac = sb + (s & 1) * BUF_FLTS;
        const float* Bc = Ac + 2560;

        #pragma unroll
        for (int kk = 0; kk < 16; kk += 8) {
            uint32_t af[4][4], bf[4][2];
            #pragma unroll
            for (int mt = 0; mt < 4; mt++) {
                const int m0 = (wm + mt * 16 + t4) * SB_STRIDE + kk + tk;
                af[mt][0] = __float_as_uint(Ac[m0]);
                af[mt][1] = __float_as_uint(Ac[m0 + 8 * SB_STRIDE]);
                af[mt][2] = __float_as_uint(Ac[m0 + 4]);
                af[mt][3] = __float_as_uint(Ac[m0 + 8 * SB_STRIDE + 4]);
            }
            #pragma unroll
            for (int nt = 0; nt < 4; nt++) {
                const int n0 = (wn + nt * 8 + t4) * SB_STRIDE + kk + tk;
                bf[nt][0] = __float_as_uint(Bc[n0]);
                bf[nt][1] = __float_as_uint(Bc[n0 + 4]);
            }
            #pragma unroll
            for (int mt = 0; mt < 4; mt++)
                #pragma unroll
                for (int nt = 0; nt < 4; nt++)
                    mma_tf32(acc[mt][nt], af[mt][0], af[mt][1], af[mt][2], af[mt][3],
                             bf[nt][0], bf[nt][1]);
        }

        if (s + 1 < ST) {
            float* Ad = sb + ((s + 1) & 1) * BUF_FLTS;
            float* Bd = Ad + 2560;
            Ad[r * SB_STRIDE + g + 0] = f2tf_f(na0.x); Ad[r * SB_STRIDE + g + 1] = f2tf_f(na0.y);
            Ad[r * SB_STRIDE + g + 2] = f2tf_f(na0.z); Ad[r * SB_STRIDE + g + 3] = f2tf_f(na0.w);
            Ad[(r + 64) * SB_STRIDE + g + 0] = f2tf_f(na1.x); Ad[(r + 64) * SB_STRIDE + g + 1] = f2tf_f(na1.y);
            Ad[(r + 64) * SB_STRIDE + g + 2] = f2tf_f(na1.z); Ad[(r + 64) * SB_STRIDE + g + 3] = f2tf_f(na1.w);
            Bd[r * SB_STRIDE + g + 0] = f2tf_f(nb0.x); Bd[r * SB_STRIDE + g + 1] = f2tf_f(nb0.y);
            Bd[r * SB_STRIDE + g + 2] = f2tf_f(nb0.z); Bd[r * SB_STRIDE + g + 3] = f2tf_f(nb0.w);
            Bd[(r + 64) * SB_STRIDE + g + 0] = f2tf_f(nb1.x); Bd[(r + 64) * SB_STRIDE + g + 1] = f2tf_f(nb1.y);
            Bd[(r + 64) * SB_STRIDE + g + 2] = f2tf_f(nb1.z); Bd[(r + 64) * SB_STRIDE + g + 3] = f2tf_f(nb1.w);
        }
        __syncthreads();
    }
}

// Write this thread's accumulator fragments into a 64-row SMEM stage (pass p selects
// which warp_m half participates). stage stride = 129 floats.
__device__ __forceinline__ void frag_to_stage(float* stage, float acc[4][4][4], int p)
{
    const int tid  = threadIdx.x;
    const int lane = tid & 31;
    const int wid  = tid >> 5;
    if ((wid >> 2) != p) return;
    const int wn = (wid & 3) * 32;
    const int t4 = lane >> 2;
    const int tc = (lane & 3) * 2;
    #pragma unroll
    for (int mt = 0; mt < 4; mt++) {
        #pragma unroll
        for (int nt = 0; nt < 4; nt++) {
            const int row = mt * 16 + t4;
            const int col = wn + nt * 8 + tc;
            stage[row * 129 + col]           = acc[mt][nt][0];
            stage[row * 129 + col + 1]       = acc[mt][nt][1];
            stage[(row + 8) * 129 + col]     = acc[mt][nt][2];
            stage[(row + 8) * 129 + col + 1] = acc[mt][nt][3];
        }
    }
}

// ---------------- GEMM1: D[m,o] = h[m,:]*wT[o,:]; store transposed -> g_hpT[z][o][n] ----------------
__global__ __launch_bounds__(256) void gemm1_tc(const float* __restrict__ h)
{
    __shared__ __align__(16) float sb[10240];
    const int o0 = blockIdx.x * 128;
    const int m0 = blockIdx.y * 128;
    const int hd = blockIdx.z;

    float acc[4][4][4];
    #pragma unroll
    for (int a = 0; a < 4; a++)
        #pragma unroll
        for (int b = 0; b < 4; b++)
            #pragma unroll
            for (int c = 0; c < 4; c++) acc[a][b][c] = 0.f;

    mm_mainloop<FIN / 16>(h + (size_t)m0 * FIN, FIN,
                          g_wT + (size_t)hd * FOUT * FIN + (size_t)o0 * FIN, FIN,
                          sb, acc);

    const int b  = m0 >> 11;
    const int n0 = m0 & (NN - 1);
    const int z  = hd * BSZ + b;
    float* dst = g_hpT + (size_t)z * FOUT * NN;
    float* stage = sb;                     // 64 x 129 floats (33024 B <= 40960 B)
    const int tid = threadIdx.x;

    #pragma unroll
    for (int p = 0; p < 2; p++) {
        frag_to_stage(stage, acc, p);
        __syncthreads();
        #pragma unroll
        for (int it = 0; it < 32; it++) {
            int idx = tid + it * 256;      // 64 n_l x 128 o
            int n_l = idx & 63;
            int o   = idx >> 6;
            dst[(size_t)(o0 + o) * NN + n0 + p * 64 + n_l] = stage[n_l * 129 + o];
        }
        __syncthreads();
    }
}

// ---------------- GEMM2: D[i,o] = attn[z][i,:]*hpT[z][o,:] + bias; store out[b][hd][i][o] ----------------
__global__ __launch_bounds__(256) void gemm2_tc(
    const float* __restrict__ bias, float* __restrict__ out)
{
    __shared__ __align__(16) float sb[10240];
    const int o0 = blockIdx.x * 128;
    const int i0 = blockIdx.y * 128;
    const int z  = blockIdx.z;

    float acc[4][4][4];
    #pragma unroll
    for (int a = 0; a < 4; a++)
        #pragma unroll
        for (int b = 0; b < 4; b++)
            #pragma unroll
            for (int c = 0; c < 4; c++) acc[a][b][c] = 0.f;

    mm_mainloop<NN / 16>(g_attn + (size_t)z * NN * NN + (size_t)i0 * NN, NN,
                         g_hpT + (size_t)z * FOUT * NN + (size_t)o0 * NN, NN,
                         sb, acc);

    const int b  = z & (BSZ - 1);
    const int hd = z >> 2;
    float* obase = out + ((size_t)(b * NH + hd) * NN + i0) * FOUT + o0;
    float* stage = sb;
    const int tid = threadIdx.x;

    #pragma unroll
    for (int p = 0; p < 2; p++) {
        frag_to_stage(stage, acc, p);
        __syncthreads();
        #pragma unroll
        for (int it = 0; it < 32; it++) {
            int idx = tid + it * 256;      // 64 rows x 128 cols
            int c   = idx & 127;
            int r_l = idx >> 7;
            obase[(size_t)(p * 64 + r_l) * FOUT + c] =
                stage[r_l * 129 + c] + __ldg(bias + o0 + c);
        }
        __syncthreads();
    }
}

// ---------------- w transpose: w[hd][f][o] -> wT[hd][o][f] ----------------
__global__ void wT_kernel(const float* __restrict__ w)
{
    __shared__ float t[32][33];
    const int hd = blockIdx.z;
    const int f0 = blockIdx.y * 32, o0 = blockIdx.x * 32;
    const int x = threadIdx.x, y = threadIdx.y;   // 32 x 8
    const float* src = w + (size_t)hd * FIN * FOUT;
    #pragma unroll
    for (int i = 0; i < 32; i += 8)
        t[y + i][x] = src[(size_t)(f0 + y + i) * FOUT + o0 + x];
    __syncthreads();
    float* dst = g_wT + (size_t)hd * FOUT * FIN;
    #pragma unroll
    for (int i = 0; i < 32; i += 8)
        dst[(size_t)(o0 + y + i) * FIN + f0 + x] = t[x][y + i];
}

// ---------------- adj dtype detection (proven) ----------------
__global__ void adj_detect_kernel(const uint32_t* __restrict__ adj_words)
{
    __shared__ int s_not01, s_notf;
    if (threadIdx.x == 0) { s_not01 = 0; s_notf = 0; }
    __syncthreads();
    int not01 = 0, notf = 0;
    const int NWORDS = 1 << 20;
    for (int i = threadIdx.x; i < NWORDS; i += blockDim.x) {
        uint32_t v = adj_words[i];
        if (v > 1u) not01 = 1;
        if (v != 0u && v != 0x3f800000u) notf = 1;
    }
    if (not01) atomicOr(&s_not01, 1);
    if (notf)  atomicOr(&s_notf, 1);
    __syncthreads();
    if (threadIdx.x == 0)
        g_adjmode = (!s_not01) ? 0 : ((!s_notf) ? 1 : 2);
}

// ---------------- attn_src/dst from hpT (coalesced: thread per n, loop o) ----------------
__global__ __launch_bounds__(128) void attvec_kernel(
    const float* __restrict__ a_src, const float* __restrict__ a_dst)
{
    __shared__ float sa[FOUT], sd[FOUT];
    const int z = blockIdx.y;
    const int hd = z >> 2;
    for (int o = threadIdx.x; o < FOUT; o += 128) {
        sa[o] = a_src[hd * FOUT + o];
        sd[o] = a_dst[hd * FOUT + o];
    }
    __syncthreads();
    const int n = blockIdx.x * 128 + threadIdx.x;
    const float* col = g_hpT + (size_t)z * FOUT * NN + n;
    float s1 = 0.f, s2 = 0.f;
    #pragma unroll 4
    for (int o = 0; o < FOUT; o++) {
        float t = tanhf(col[(size_t)o * NN]);
        s1 += t * sa[o];
        s2 += t * sd[o];
    }
    g_src[z * NN + n] = s1;
    g_dst[z * NN + n] = s2;
}

// ---------------- masked softmax (register-resident values) ----------------
__global__ __launch_bounds__(256) void softmax_kernel(const void* __restrict__ adj)
{
    __shared__ float sdst[NN];
    __shared__ float redm[8], reds[8], bcast[2];

    const int z = blockIdx.y;
    const int i = blockIdx.x;
    const int b = z & (BSZ - 1);
    const int tid = threadIdx.x, lane = tid & 31, wid = tid >> 5;

    const float* dstrow = g_dst + (size_t)z * NN;
    for (int j = tid * 4; j < NN; j += 256 * 4)
        *(float4*)&sdst[j] = *(const float4*)&dstrow[j];
    __syncthreads();

    const float srcv = g_src[(size_t)z * NN + i];
    const size_t rowbase = ((size_t)b * NN + i) * NN;
    const int j0 = tid * 8;

    uint32_t keep8 = 0;
    const int mode = g_adjmode;
    if (mode == 0) {
        const int* arow = (const int*)adj + rowbase;
        int4 w0 = *(const int4*)(arow + j0);
        int4 w1 = *(const int4*)(arow + j0 + 4);
        keep8 = (w0.x != 0) | ((w0.y != 0) << 1) | ((w0.z != 0) << 2) | ((w0.w != 0) << 3)
              | ((w1.x != 0) << 4) | ((w1.y != 0) << 5) | ((w1.z != 0) << 6) | ((w1.w != 0) << 7);
    } else if (mode == 1) {
        const float* arow = (const float*)adj + rowbase;
        float4 w0 = *(const float4*)(arow + j0);
        float4 w1 = *(const float4*)(arow + j0 + 4);
        keep8 = (w0.x != 0.f) | ((w0.y != 0.f) << 1) | ((w0.z != 0.f) << 2) | ((w0.w != 0.f) << 3)
              | ((w1.x != 0.f) << 4) | ((w1.y != 0.f) << 5) | ((w1.z != 0.f) << 6) | ((w1.w != 0.f) << 7);
    } else {
        const uint8_t* arow = (const uint8_t*)adj + rowbase;
        uint2 mraw = *(const uint2*)(arow + j0);
        #pragma unroll
        for (int u = 0; u < 4; u++) {
            keep8 |= (((mraw.x >> (8 * u)) & 0xffu) != 0u) << u;
            keep8 |= (((mraw.y >> (8 * u)) & 0xffu) != 0u) << (u + 4);
        }
    }

    float v[8];
    float mx = NEG_INF;
    #pragma unroll
    for (int u = 0; u < 8; u++) {
        int j = j0 + u;
        bool keep = ((keep8 >> u) & 1u) || (j == i);
        float s = srcv + sdst[j];
        s = (s >= 0.f) ? s : NEG_SLOPE * s;
        v[u] = keep ? s : NEG_INF;
        mx = fmaxf(mx, v[u]);
    }

    #pragma unroll
    for (int off = 16; off; off >>= 1) mx = fmaxf(mx, __shfl_xor_sync(0xffffffffu, mx, off));
    if (lane == 0) redm[wid] = mx;
    __syncthreads();
    if (tid < 8) {
        float x = redm[tid];
        #pragma unroll
        for (int off = 4; off; off >>= 1) x = fmaxf(x, __shfl_xor_sync(0xffu, x, off));
        if (tid == 0) bcast[0] = x;
    }
    __syncthreads();
    const float smax = bcast[0];

    float lsum = 0.f;
    #pragma unroll
    for (int u = 0; u < 8; u++) {
        float e = (v[u] == NEG_INF) ? 0.f : __expf(v[u] - smax);
        v[u] = e;
        lsum += e;
    }
    #pragma unroll
    for (int off = 16; off; off >>= 1) lsum += __shfl_xor_sync(0xffffffffu, lsum, off);
    if (lane == 0) reds[wid] = lsum;
    __syncthreads();
    if (tid < 8) {
        float x = reds[tid];
        #pragma unroll
        for (int off = 4; off; off >>= 1) x += __shfl_xor_sync(0xffu, x, off);
        if (tid == 0) bcast[1] = 1.f / x;
    }
    __syncthreads();
    const float inv = bcast[1];

    float* outrow = g_attn + ((size_t)z * NN + i) * NN;
    #pragma unroll
    for (int u = 0; u < 8; u += 4) {
        float4 o4;
        o4.x = v[u + 0] * inv; o4.y = v[u + 1] * inv;
        o4.z = v[u + 2] * inv; o4.w = v[u + 3] * inv;
        *(float4*)(outrow + j0 + u) = o4;
    }
}

// ---------------- launch ----------------
extern "C" void kernel_launch(void* const* d_in, const int* in_sizes, int n_in,
                              void* d_out, int out_size)
{
    const float *h = nullptr, *w = nullptr, *a_src = nullptr, *a_dst = nullptr, *bias = nullptr;
    const void  *adj = nullptr;
    for (int k = 0; k < n_in; k++) {
        switch (in_sizes[k]) {
            case BSZ * NN * FIN:  h   = (const float*)d_in[k]; break;
            case BSZ * NN * NN:   adj = d_in[k];               break;
            case NH * FIN * FOUT: w   = (const float*)d_in[k]; break;
            case NH * FOUT:       if (!a_src) a_src = (const float*)d_in[k];
                                  else        a_dst = (const float*)d_in[k]; break;
            case FOUT:            bias = (const float*)d_in[k]; break;
            default: break;
        }
    }
    float* out = (float*)d_out;

    adj_detect_kernel<<<1, 256>>>((const uint32_t*)adj);

    dim3 gw(FOUT / 32, FIN / 32, NH);
    wT_kernel<<<gw, dim3(32, 8)>>>(w);

    dim3 g1(FOUT / 128, (BSZ * NN) / 128, NH);            // (6, 64, 2)
    gemm1_tc<<<g1, 256>>>(h);

    attvec_kernel<<<dim3(NN / 128, NH * BSZ), 128>>>(a_src, a_dst);

    softmax_kernel<<<dim3(NN, NH * BSZ), 256>>>(adj);

    dim3 g2(FOUT / 128, NN / 128, NH * BSZ);              // (6, 16, 8)
    gemm2_tc<<<g2, 256>>>(bias, out);
}

// round 16
// speedup vs baseline: 1.9561x; 1.1910x over previous
#include <cuda_runtime.h>
#include <cstdint>

#define BSZ  4
#define NN   2048
#define NH   2
#define FIN  768
#define FOUT 768
#define NEG_SLOPE 0.2f
#define NEG_INF (__int_as_float(0xff800000))

// ---------------- scratch (allocation-free: __device__ globals) ----------------
__device__ __align__(16) float g_hpT[(size_t)NH * BSZ * FOUT * NN]; // [z][o][n] tf32-rounded
__device__ __align__(16) float g_attn[(size_t)NH * BSZ * NN * NN];  // [z][i][j] tf32-rounded
__device__ __align__(16) float g_wT[(size_t)NH * FOUT * FIN];       // [hd][o][f] tf32-rounded
__device__ __align__(16) float g_hR[(size_t)BSZ * NN * FIN];        // tf32-rounded copy of h
__device__ float g_src[NH * BSZ * NN];
__device__ float g_dst[NH * BSZ * NN];
__device__ int   g_adjmode;

// ---------------- helpers (portable sm_80+ PTX) ----------------
__device__ __forceinline__ float f2tf_f(float x) {   // fp32 -> tf32 (RN), bits in float reg
    uint32_t r;
    asm("cvt.rna.tf32.f32 %0, %1;" : "=r"(r) : "f"(x));
    return __uint_as_float(r);
}
__device__ __forceinline__ uint32_t smem_u32(const void* p) {
    uint32_t a;
    asm("{ .reg .u64 t; cvta.to.shared.u64 t, %1; cvt.u32.u64 %0, t; }" : "=r"(a) : "l"(p));
    return a;
}
__device__ __forceinline__ void cp16(uint32_t saddr, const void* gptr) {
    asm volatile("cp.async.ca.shared.global [%0], [%1], 16;" :: "r"(saddr), "l"(gptr));
}
#define CP_COMMIT() asm volatile("cp.async.commit_group;" ::: "memory")
#define CP_WAIT1()  asm volatile("cp.async.wait_group 1;" ::: "memory")

__device__ __forceinline__ void mma_tf32(float* c, uint32_t a0, uint32_t a1,
                                         uint32_t a2, uint32_t a3,
                                         uint32_t b0, uint32_t b1) {
    asm volatile(
        "mma.sync.aligned.m16n8k8.row.col.f32.tf32.tf32.f32 "
        "{%0,%1,%2,%3}, {%4,%5,%6,%7}, {%8,%9}, {%0,%1,%2,%3};"
        : "+f"(c[0]), "+f"(c[1]), "+f"(c[2]), "+f"(c[3])
        : "r"(a0), "r"(a1), "r"(a2), "r"(a3), "r"(b0), "r"(b1));
}

// SMEM: per stage A[128][20] + B[128][20]; 3 stages (dynamic smem, 61440 B).
#define SB_STRIDE 20
#define OP_FLTS   (128 * SB_STRIDE)       // 2560
#define STAGE_FLTS (2 * OP_FLTS)          // 5120
#define DSM_BYTES (3 * STAGE_FLTS * 4)    // 61440

extern __shared__ float dsm[];

// ---------------- cp.async 3-stage mainloop: acc += A[128,K] * B[128,K]^T ----------------
// A, B pre-offset to 128-row tile origin, K-major, pre-rounded to tf32. K = ST*16.
template <int ST>
__device__ __forceinline__ void mm_mainloop(
    const float* __restrict__ A, int lda,
    const float* __restrict__ B, int ldb,
    float acc[4][4][4])
{
    const int tid  = threadIdx.x;
    const int lane = tid & 31;
    const int wid  = tid >> 5;
    const int wm   = (wid >> 2) * 64;
    const int wn   = (wid & 3) * 32;
    const int t4   = lane >> 2;
    const int tk   = lane & 3;

    const int r = tid >> 2;               // 0..63
    const int g = (tid & 3) * 4;          // 0,4,8,12

    const float* Ap0 = A + (size_t)r * lda + g;
    const float* Ap1 = A + (size_t)(r + 64) * lda + g;
    const float* Bp0 = B + (size_t)r * ldb + g;
    const float* Bp1 = B + (size_t)(r + 64) * ldb + g;

    const uint32_t sbase = smem_u32(dsm);
    const uint32_t offA0 = (r * SB_STRIDE + g) * 4;
    const uint32_t offA1 = ((r + 64) * SB_STRIDE + g) * 4;
    const uint32_t offB0 = (OP_FLTS + r * SB_STRIDE + g) * 4;
    const uint32_t offB1 = (OP_FLTS + (r + 64) * SB_STRIDE + g) * 4;

    #define ISSUE(s) do { \
        const uint32_t bo = (uint32_t)(((s) % 3) * STAGE_FLTS * 4); \
        const int k0 = (s) * 16; \
        cp16(sbase + bo + offA0, Ap0 + k0); \
        cp16(sbase + bo + offA1, Ap1 + k0); \
        cp16(sbase + bo + offB0, Bp0 + k0); \
        cp16(sbase + bo + offB1, Bp1 + k0); \
    } while (0)

    ISSUE(0); CP_COMMIT();
    ISSUE(1); CP_COMMIT();

    for (int s = 0; s < ST; s++) {
        CP_WAIT1();               // group s complete (≤1 outstanding)
        __syncthreads();

        const float* Ac = dsm + (s % 3) * STAGE_FLTS;
        const float* Bc = Ac + OP_FLTS;

        #pragma unroll
        for (int kk = 0; kk < 16; kk += 8) {
            uint32_t af[4][4], bf[4][2];
            #pragma unroll
            for (int mt = 0; mt < 4; mt++) {
                const int m0 = (wm + mt * 16 + t4) * SB_STRIDE + kk + tk;
                af[mt][0] = __float_as_uint(Ac[m0]);
                af[mt][1] = __float_as_uint(Ac[m0 + 8 * SB_STRIDE]);
                af[mt][2] = __float_as_uint(Ac[m0 + 4]);
                af[mt][3] = __float_as_uint(Ac[m0 + 8 * SB_STRIDE + 4]);
            }
            #pragma unroll
            for (int nt = 0; nt < 4; nt++) {
                const int n0 = (wn + nt * 8 + t4) * SB_STRIDE + kk + tk;
                bf[nt][0] = __float_as_uint(Bc[n0]);
                bf[nt][1] = __float_as_uint(Bc[n0 + 4]);
            }
            #pragma unroll
            for (int mt = 0; mt < 4; mt++)
                #pragma unroll
                for (int nt = 0; nt < 4; nt++)
                    mma_tf32(acc[mt][nt], af[mt][0], af[mt][1], af[mt][2], af[mt][3],
                             bf[nt][0], bf[nt][1]);
        }

        if (s + 2 < ST) ISSUE(s + 2);
        CP_COMMIT();              // always commit (possibly empty) so WAIT1 drains the tail
    }
    __syncthreads();              // protect epilogue smem reuse
    #undef ISSUE
}

// Accumulator fragments -> 64-row SMEM stage (pass p = warp_m half). stride 129.
__device__ __forceinline__ void frag_to_stage(float* stage, float acc[4][4][4], int p)
{
    const int tid  = threadIdx.x;
    const int lane = tid & 31;
    const int wid  = tid >> 5;
    if ((wid >> 2) != p) return;
    const int wn = (wid & 3) * 32;
    const int t4 = lane >> 2;
    const int tc = (lane & 3) * 2;
    #pragma unroll
    for (int mt = 0; mt < 4; mt++) {
        #pragma unroll
        for (int nt = 0; nt < 4; nt++) {
            const int row = mt * 16 + t4;
            const int col = wn + nt * 8 + tc;
            stage[row * 129 + col]           = acc[mt][nt][0];
            stage[row * 129 + col + 1]       = acc[mt][nt][1];
            stage[(row + 8) * 129 + col]     = acc[mt][nt][2];
            stage[(row + 8) * 129 + col + 1] = acc[mt][nt][3];
        }
    }
}

// ---------------- GEMM1: D[m,o] = hR[m,:]*wT[o,:]; store tf32-rounded hpT[z][o][n] ----------------
__global__ __launch_bounds__(256) void gemm1_tc()
{
    const int o0 = blockIdx.x * 128;
    const int m0 = blockIdx.y * 128;
    const int hd = blockIdx.z;

    float acc[4][4][4];
    #pragma unroll
    for (int a = 0; a < 4; a++)
        #pragma unroll
        for (int b = 0; b < 4; b++)
            #pragma unroll
            for (int c = 0; c < 4; c++) acc[a][b][c] = 0.f;

    mm_mainloop<FIN / 16>(g_hR + (size_t)m0 * FIN, FIN,
                          g_wT + (size_t)hd * FOUT * FIN + (size_t)o0 * FIN, FIN, acc);

    const int b  = m0 >> 11;
    const int n0 = m0 & (NN - 1);
    const int z  = hd * BSZ + b;
    float* dst = g_hpT + (size_t)z * FOUT * NN;
    float* stage = dsm;
    const int tid = threadIdx.x;

    #pragma unroll
    for (int p = 0; p < 2; p++) {
        frag_to_stage(stage, acc, p);
        __syncthreads();
        #pragma unroll
        for (int it = 0; it < 32; it++) {
            int idx = tid + it * 256;      // 64 n_l x 128 o
            int n_l = idx & 63;
            int o   = idx >> 6;
            dst[(size_t)(o0 + o) * NN + n0 + p * 64 + n_l] = f2tf_f(stage[n_l * 129 + o]);
        }
        __syncthreads();
    }
}

// ---------------- GEMM2: D[i,o] = attn[z][i,:]*hpT[z][o,:] + bias -> out[b][hd][i][o] ----------------
__global__ __launch_bounds__(256) void gemm2_tc(
    const float* __restrict__ bias, float* __restrict__ out)
{
    const int o0 = blockIdx.x * 128;
    const int i0 = blockIdx.y * 128;
    const int z  = blockIdx.z;

    float acc[4][4][4];
    #pragma unroll
    for (int a = 0; a < 4; a++)
        #pragma unroll
        for (int b = 0; b < 4; b++)
            #pragma unroll
            for (int c = 0; c < 4; c++) acc[a][b][c] = 0.f;

    mm_mainloop<NN / 16>(g_attn + (size_t)z * NN * NN + (size_t)i0 * NN, NN,
                         g_hpT + (size_t)z * FOUT * NN + (size_t)o0 * NN, NN, acc);

    const int b  = z & (BSZ - 1);
    const int hd = z >> 2;
    float* obase = out + ((size_t)(b * NH + hd) * NN + i0) * FOUT + o0;
    float* stage = dsm;
    const int tid = threadIdx.x;

    #pragma unroll
    for (int p = 0; p < 2; p++) {
        frag_to_stage(stage, acc, p);
        __syncthreads();
        #pragma unroll
        for (int it = 0; it < 32; it++) {
            int idx = tid + it * 256;      // 64 rows x 128 cols
            int c   = idx & 127;
            int r_l = idx >> 7;
            obase[(size_t)(p * 64 + r_l) * FOUT + c] =
                stage[r_l * 129 + c] + __ldg(bias + o0 + c);
        }
        __syncthreads();
    }
}

// ---------------- h -> tf32-rounded copy ----------------
__global__ void hR_kernel(const float* __restrict__ h)
{
    size_t i = ((size_t)blockIdx.x * 256 + threadIdx.x) * 4;
    float4 v = *(const float4*)(h + i);
    float4 o;
    o.x = f2tf_f(v.x); o.y = f2tf_f(v.y); o.z = f2tf_f(v.z); o.w = f2tf_f(v.w);
    *(float4*)(g_hR + i) = o;
}

// ---------------- w transpose + tf32 round: w[hd][f][o] -> wT[hd][o][f] ----------------
__global__ void wT_kernel(const float* __restrict__ w)
{
    __shared__ float t[32][33];
    const int hd = blockIdx.z;
    const int f0 = blockIdx.y * 32, o0 = blockIdx.x * 32;
    const int x = threadIdx.x, y = threadIdx.y;   // 32 x 8
    const float* src = w + (size_t)hd * FIN * FOUT;
    #pragma unroll
    for (int i = 0; i < 32; i += 8)
        t[y + i][x] = src[(size_t)(f0 + y + i) * FOUT + o0 + x];
    __syncthreads();
    float* dst = g_wT + (size_t)hd * FOUT * FIN;
    #pragma unroll
    for (int i = 0; i < 32; i += 8)
        dst[(size_t)(o0 + y + i) * FIN + f0 + x] = f2tf_f(t[x][y + i]);
}

// ---------------- adj dtype detection (proven) ----------------
__global__ void adj_detect_kernel(const uint32_t* __restrict__ adj_words)
{
    __shared__ int s_not01, s_notf;
    if (threadIdx.x == 0) { s_not01 = 0; s_notf = 0; }
    __syncthreads();
    int not01 = 0, notf = 0;
    const int NWORDS = 1 << 20;
    for (int i = threadIdx.x; i < NWORDS; i += blockDim.x) {
        uint32_t v = adj_words[i];
        if (v > 1u) not01 = 1;
        if (v != 0u && v != 0x3f800000u) notf = 1;
    }
    if (not01) atomicOr(&s_not01, 1);
    if (notf)  atomicOr(&s_notf, 1);
    __syncthreads();
    if (threadIdx.x == 0)
        g_adjmode = (!s_not01) ? 0 : ((!s_notf) ? 1 : 2);
}

// ---------------- attn_src/dst: 4-way o-split, SMEM reduce (occ fix) ----------------
__global__ __launch_bounds__(256) void attvec_kernel(
    const float* __restrict__ a_src, const float* __restrict__ a_dst)
{
    __shared__ float sa[FOUT], sd[FOUT];
    __shared__ float p1[4][64], p2[4][64];
    const int z  = blockIdx.y;
    const int hd = z >> 2;
    for (int o = threadIdx.x; o < FOUT; o += 256) {
        sa[o] = a_src[hd * FOUT + o];
        sd[o] = a_dst[hd * FOUT + o];
    }
    __syncthreads();

    const int n_l = threadIdx.x & 63;
    const int oc  = threadIdx.x >> 6;                 // 0..3, 192 o's each
    const int n   = blockIdx.x * 64 + n_l;
    const float* col = g_hpT + (size_t)z * FOUT * NN + n;

    float s1 = 0.f, s2 = 0.f;
    const int obeg = oc * 192;
    #pragma unroll 4
    for (int o = obeg; o < obeg + 192; o++) {
        float t = tanhf(col[(size_t)o * NN]);
        s1 += t * sa[o];
        s2 += t * sd[o];
    }
    p1[oc][n_l] = s1;
    p2[oc][n_l] = s2;
    __syncthreads();

    if (threadIdx.x < 64) {
        int t = threadIdx.x;
        g_src[z * NN + blockIdx.x * 64 + t] = p1[0][t] + p1[1][t] + p1[2][t] + p1[3][t];
    } else if (threadIdx.x < 128) {
        int t = threadIdx.x - 64;
        g_dst[z * NN + blockIdx.x * 64 + t] = p2[0][t] + p2[1][t] + p2[2][t] + p2[3][t];
    }
}

// ---------------- masked softmax (register-resident; writes tf32-rounded attn) ----------------
__global__ __launch_bounds__(256) void softmax_kernel(const void* __restrict__ adj)
{
    __shared__ float sdst[NN];
    __shared__ float redm[8], reds[8], bcast[2];

    const int z = blockIdx.y;
    const int i = blockIdx.x;
    const int b = z & (BSZ - 1);
    const int tid = threadIdx.x, lane = tid & 31, wid = tid >> 5;

    const float* dstrow = g_dst + (size_t)z * NN;
    for (int j = tid * 4; j < NN; j += 256 * 4)
        *(float4*)&sdst[j] = *(const float4*)&dstrow[j];
    __syncthreads();

    const float srcv = g_src[(size_t)z * NN + i];
    const size_t rowbase = ((size_t)b * NN + i) * NN;
    const int j0 = tid * 8;

    uint32_t keep8 = 0;
    const int mode = g_adjmode;
    if (mode == 0) {
        const int* arow = (const int*)adj + rowbase;
        int4 w0 = *(const int4*)(arow + j0);
        int4 w1 = *(const int4*)(arow + j0 + 4);
        keep8 = (w0.x != 0) | ((w0.y != 0) << 1) | ((w0.z != 0) << 2) | ((w0.w != 0) << 3)
              | ((w1.x != 0) << 4) | ((w1.y != 0) << 5) | ((w1.z != 0) << 6) | ((w1.w != 0) << 7);
    } else if (mode == 1) {
        const float* arow = (const float*)adj + rowbase;
        float4 w0 = *(const float4*)(arow + j0);
        float4 w1 = *(const float4*)(arow + j0 + 4);
        keep8 = (w0.x != 0.f) | ((w0.y != 0.f) << 1) | ((w0.z != 0.f) << 2) | ((w0.w != 0.f) << 3)
              | ((w1.x != 0.f) << 4) | ((w1.y != 0.f) << 5) | ((w1.z != 0.f) << 6) | ((w1.w != 0.f) << 7);
    } else {
        const uint8_t* arow = (const uint8_t*)adj + rowbase;
        uint2 mraw = *(const uint2*)(arow + j0);
        #pragma unroll
        for (int u = 0; u < 4; u++) {
            keep8 |= (((mraw.x >> (8 * u)) & 0xffu) != 0u) << u;
            keep8 |= (((mraw.y >> (8 * u)) & 0xffu) != 0u) << (u + 4);
        }
    }

    float v[8];
    float mx = NEG_INF;
    #pragma unroll
    for (int u = 0; u < 8; u++) {
        int j = j0 + u;
        bool keep = ((keep8 >> u) & 1u) || (j == i);
        float s = srcv + sdst[j];
        s = (s >= 0.f) ? s : NEG_SLOPE * s;
        v[u] = keep ? s : NEG_INF;
        mx = fmaxf(mx, v[u]);
    }

    #pragma unroll
    for (int off = 16; off; off >>= 1) mx = fmaxf(mx, __shfl_xor_sync(0xffffffffu, mx, off));
    if (lane == 0) redm[wid] = mx;
    __syncthreads();
    if (tid < 8) {
        float x = redm[tid];
        #pragma unroll
        for (int off = 4; off; off >>= 1) x = fmaxf(x, __shfl_xor_sync(0xffu, x, off));
        if (tid == 0) bcast[0] = x;
    }
    __syncthreads();
    const float smax = bcast[0];

    float lsum = 0.f;
    #pragma unroll
    for (int u = 0; u < 8; u++) {
        float e = (v[u] == NEG_INF) ? 0.f : __expf(v[u] - smax);
        v[u] = e;
        lsum += e;
    }
    #pragma unroll
    for (int off = 16; off; off >>= 1) lsum += __shfl_xor_sync(0xffffffffu, lsum, off);
    if (lane == 0) reds[wid] = lsum;
    __syncthreads();
    if (tid < 8) {
        float x = reds[tid];
        #pragma unroll
        for (int off = 4; off; off >>= 1) x += __shfl_xor_sync(0xffu, x, off);
        if (tid == 0) bcast[1] = 1.f / x;
    }
    __syncthreads();
    const float inv = bcast[1];

    float* outrow = g_attn + ((size_t)z * NN + i) * NN;
    #pragma unroll
    for (int u = 0; u < 8; u += 4) {
        float4 o4;
        o4.x = f2tf_f(v[u + 0] * inv); o4.y = f2tf_f(v[u + 1] * inv);
        o4.z = f2tf_f(v[u + 2] * inv); o4.w = f2tf_f(v[u + 3] * inv);
        *(float4*)(outrow + j0 + u) = o4;
    }
}

// ---------------- launch ----------------
extern "C" void kernel_launch(void* const* d_in, const int* in_sizes, int n_in,
                              void* d_out, int out_size)
{
    const float *h = nullptr, *w = nullptr, *a_src = nullptr, *a_dst = nullptr, *bias = nullptr;
    const void  *adj = nullptr;
    for (int k = 0; k < n_in; k++) {
        switch (in_sizes[k]) {
            case BSZ * NN * FIN:  h   = (const float*)d_in[k]; break;
            case BSZ * NN * NN:   adj = d_in[k];               break;
            case NH * FIN * FOUT: w   = (const float*)d_in[k]; break;
            case NH * FOUT:       if (!a_src) a_src = (const float*)d_in[k];
                                  else        a_dst = (const float*)d_in[k]; break;
            case FOUT:            bias = (const float*)d_in[k]; break;
            default: break;
        }
    }
    float* out = (float*)d_out;

    cudaFuncSetAttribute(gemm1_tc, cudaFuncAttributeMaxDynamicSharedMemorySize, DSM_BYTES);
    cudaFuncSetAttribute(gemm2_tc, cudaFuncAttributeMaxDynamicSharedMemorySize, DSM_BYTES);

    adj_detect_kernel<<<1, 256>>>((const uint32_t*)adj);

    hR_kernel<<<(BSZ * NN * FIN) / (256 * 4), 256>>>(h);

    dim3 gw(FOUT / 32, FIN / 32, NH);
    wT_kernel<<<gw, dim3(32, 8)>>>(w);

    dim3 g1(FOUT / 128, (BSZ * NN) / 128, NH);            // (6, 64, 2)
    gemm1_tc<<<g1, 256, DSM_BYTES>>>();

    attvec_kernel<<<dim3(NN / 64, NH * BSZ), 256>>>(a_src, a_dst);

    softmax_kernel<<<dim3(NN, NH * BSZ), 256>>>(adj);

    dim3 g2(FOUT / 128, NN / 128, NH * BSZ);              // (6, 16, 8)
    gemm2_tc<<<g2, 256, DSM_BYTES>>>(bias, out);
}

// round 17
// speedup vs baseline: 2.7019x; 1.3813x over previous
#include <cuda_runtime.h>
#include <cstdint>

#define BSZ  4
#define NN   2048
#define NH   2
#define FIN  768
#define FOUT 768
#define NEG_SLOPE 0.2f
#define NEG_INF (__int_as_float(0xff800000))

// ---------------- scratch (allocation-free: __device__ globals) ----------------
__device__ __align__(16) float g_hpT[(size_t)NH * BSZ * FOUT * NN]; // [z][o][n] tf32-rounded
__device__ __align__(16) float g_attn[(size_t)NH * BSZ * NN * NN];  // [z][i][j] tf32-rounded
__device__ __align__(16) float g_wT[(size_t)NH * FOUT * FIN];       // [hd][o][f] tf32-rounded
__device__ __align__(16) float g_hR[(size_t)BSZ * NN * FIN];        // tf32-rounded copy of h
__device__ float g_src[NH * BSZ * NN];
__device__ float g_dst[NH * BSZ * NN];
__device__ int   g_adjmode;
__device__ int   g_n01, g_nf;

// ---------------- helpers (portable sm_80+ PTX) ----------------
__device__ __forceinline__ float f2tf_f(float x) {
    uint32_t r;
    asm("cvt.rna.tf32.f32 %0, %1;" : "=r"(r) : "f"(x));
    return __uint_as_float(r);
}
__device__ __forceinline__ uint32_t smem_u32(const void* p) {
    uint32_t a;
    asm("{ .reg .u64 t; cvta.to.shared.u64 t, %1; cvt.u32.u64 %0, t; }" : "=r"(a) : "l"(p));
    return a;
}
__device__ __forceinline__ void cp16(uint32_t saddr, const void* gptr) {
    asm volatile("cp.async.ca.shared.global [%0], [%1], 16;" :: "r"(saddr), "l"(gptr));
}
#define CP_COMMIT() asm volatile("cp.async.commit_group;" ::: "memory")
#define CP_WAIT1()  asm volatile("cp.async.wait_group 1;" ::: "memory")

__device__ __forceinline__ void mma_tf32(float* c, uint32_t a0, uint32_t a1,
                                         uint32_t a2, uint32_t a3,
                                         uint32_t b0, uint32_t b1) {
    asm volatile(
        "mma.sync.aligned.m16n8k8.row.col.f32.tf32.tf32.f32 "
        "{%0,%1,%2,%3}, {%4,%5,%6,%7}, {%8,%9}, {%0,%1,%2,%3};"
        : "+f"(c[0]), "+f"(c[1]), "+f"(c[2]), "+f"(c[3])
        : "r"(a0), "r"(a1), "r"(a2), "r"(a3), "r"(b0), "r"(b1));
}

// SMEM: per stage A[128][36] + B[128][36]; 3 stages (dynamic, 110592 B).
#define SB_STRIDE 36
#define OP_FLTS   (128 * SB_STRIDE)        // 4608
#define STAGE_FLTS (2 * OP_FLTS)           // 9216
#define DSM_BYTES (3 * STAGE_FLTS * 4)     // 110592

extern __shared__ float dsm[];

// ---------------- cp.async 3-stage mainloop, 512 thr, BK=32, warp tile 32x32 ----------------
// acc[2][4][4] += A[128,K] * B[128,K]^T.  A,B tile-origin, K-major, pre-rounded. K = ST*32.
template <int ST>
__device__ __forceinline__ void mm_mainloop(
    const float* __restrict__ A, int lda,
    const float* __restrict__ B, int ldb,
    float acc[2][4][4])
{
    const int tid  = threadIdx.x;
    const int lane = tid & 31;
    const int wid  = tid >> 5;               // 0..15
    const int wm   = (wid >> 2) * 32;        // 0,32,64,96
    const int wn   = (wid & 3) * 32;         // 0,32,64,96
    const int t4   = lane >> 2;              // 0..7
    const int tk   = lane & 3;               // 0..3

    const int r = tid >> 3;                  // 0..63
    const int g = (tid & 7) * 4;             // 0..28

    const float* Ap0 = A + (size_t)r * lda + g;
    const float* Ap1 = A + (size_t)(r + 64) * lda + g;
    const float* Bp0 = B + (size_t)r * ldb + g;
    const float* Bp1 = B + (size_t)(r + 64) * ldb + g;

    const uint32_t sbase = smem_u32(dsm);
    const uint32_t offA0 = (r * SB_STRIDE + g) * 4;
    const uint32_t offA1 = ((r + 64) * SB_STRIDE + g) * 4;
    const uint32_t offB0 = (OP_FLTS + r * SB_STRIDE + g) * 4;
    const uint32_t offB1 = (OP_FLTS + (r + 64) * SB_STRIDE + g) * 4;

    #define ISSUE(s) do { \
        const uint32_t bo = (uint32_t)(((s) % 3) * STAGE_FLTS * 4); \
        const int k0 = (s) * 32; \
        cp16(sbase + bo + offA0, Ap0 + k0); \
        cp16(sbase + bo + offA1, Ap1 + k0); \
        cp16(sbase + bo + offB0, Bp0 + k0); \
        cp16(sbase + bo + offB1, Bp1 + k0); \
    } while (0)

    #define LDFRAG(dst_a, dst_b, kk) do { \
        _Pragma("unroll") \
        for (int mt = 0; mt < 2; mt++) { \
            const int m0 = (wm + mt * 16 + t4) * SB_STRIDE + (kk) + tk; \
            dst_a[mt][0] = __float_as_uint(Ac[m0]); \
            dst_a[mt][1] = __float_as_uint(Ac[m0 + 8 * SB_STRIDE]); \
            dst_a[mt][2] = __float_as_uint(Ac[m0 + 4]); \
            dst_a[mt][3] = __float_as_uint(Ac[m0 + 8 * SB_STRIDE + 4]); \
        } \
        _Pragma("unroll") \
        for (int nt = 0; nt < 4; nt++) { \
            const int n0 = (wn + nt * 8 + t4) * SB_STRIDE + (kk) + tk; \
            dst_b[nt][0] = __float_as_uint(Bc[n0]); \
            dst_b[nt][1] = __float_as_uint(Bc[n0 + 4]); \
        } \
    } while (0)

    ISSUE(0); CP_COMMIT();
    ISSUE(1); CP_COMMIT();

    for (int s = 0; s < ST; s++) {
        CP_WAIT1();
        __syncthreads();

        const float* Ac = dsm + (s % 3) * STAGE_FLTS;
        const float* Bc = Ac + OP_FLTS;

        uint32_t afA[2][4], bfA[4][2], afB[2][4], bfB[4][2];
        LDFRAG(afA, bfA, 0);

        #pragma unroll
        for (int kk = 0; kk < 4; kk++) {
            if (kk & 1) {
                if (kk < 3) LDFRAG(afA, bfA, (kk + 1) * 8);
                #pragma unroll
                for (int mt = 0; mt < 2; mt++)
                    #pragma unroll
                    for (int nt = 0; nt < 4; nt++)
                        mma_tf32(acc[mt][nt], afB[mt][0], afB[mt][1], afB[mt][2], afB[mt][3],
                                 bfB[nt][0], bfB[nt][1]);
            } else {
                LDFRAG(afB, bfB, (kk + 1) * 8);   // kk=0 -> load 8; kk=2 -> load 24
                #pragma unroll
                for (int mt = 0; mt < 2; mt++)
                    #pragma unroll
                    for (int nt = 0; nt < 4; nt++)
                        mma_tf32(acc[mt][nt], afA[mt][0], afA[mt][1], afA[mt][2], afA[mt][3],
                                 bfA[nt][0], bfA[nt][1]);
            }
        }

        if (s + 2 < ST) ISSUE(s + 2);
        CP_COMMIT();
    }
    __syncthreads();
    #undef ISSUE
    #undef LDFRAG
}

// Accumulator fragments -> full 128x129 SMEM stage (single pass, 16 warps).
__device__ __forceinline__ void frag_to_stage(float* stage, float acc[2][4][4])
{
    const int lane = threadIdx.x & 31;
    const int wid  = threadIdx.x >> 5;
    const int wm = (wid >> 2) * 32;
    const int wn = (wid & 3) * 32;
    const int t4 = lane >> 2;
    const int tc = (lane & 3) * 2;
    #pragma unroll
    for (int mt = 0; mt < 2; mt++) {
        #pragma unroll
        for (int nt = 0; nt < 4; nt++) {
            const int row = wm + mt * 16 + t4;
            const int col = wn + nt * 8 + tc;
            stage[row * 129 + col]           = acc[mt][nt][0];
            stage[row * 129 + col + 1]       = acc[mt][nt][1];
            stage[(row + 8) * 129 + col]     = acc[mt][nt][2];
            stage[(row + 8) * 129 + col + 1] = acc[mt][nt][3];
        }
    }
}

// ---------------- GEMM1: D[m,o] = hR[m,:]*wT[o,:]; store tf32-rounded hpT[z][o][n] ----------------
__global__ __launch_bounds__(512, 1) void gemm1_tc()
{
    const int o0 = blockIdx.x * 128;
    const int m0 = blockIdx.y * 128;
    const int hd = blockIdx.z;

    float acc[2][4][4];
    #pragma unroll
    for (int a = 0; a < 2; a++)
        #pragma unroll
        for (int b = 0; b < 4; b++)
            #pragma unroll
            for (int c = 0; c < 4; c++) acc[a][b][c] = 0.f;

    mm_mainloop<FIN / 32>(g_hR + (size_t)m0 * FIN, FIN,
                          g_wT + (size_t)hd * FOUT * FIN + (size_t)o0 * FIN, FIN, acc);

    const int b  = m0 >> 11;
    const int n0 = m0 & (NN - 1);
    const int z  = hd * BSZ + b;
    float* dst = g_hpT + (size_t)z * FOUT * NN;
    float* stage = dsm;                         // 128 x 129 = 66048 B <= 110592 B
    const int tid = threadIdx.x;

    frag_to_stage(stage, acc);
    __syncthreads();
    #pragma unroll
    for (int it = 0; it < 32; it++) {
        int idx = tid + it * 512;               // 128 n_l x 128 o
        int n_l = idx & 127;
        int o   = idx >> 7;
        dst[(size_t)(o0 + o) * NN + n0 + n_l] = f2tf_f(stage[n_l * 129 + o]);
    }
}

// ---------------- GEMM2: D[i,o] = attn[z][i,:]*hpT[z][o,:] + bias -> out[b][hd][i][o] ----------------
__global__ __launch_bounds__(512, 1) void gemm2_tc(
    const float* __restrict__ bias, float* __restrict__ out)
{
    const int o0 = blockIdx.x * 128;
    const int i0 = blockIdx.y * 128;
    const int z  = blockIdx.z;

    float acc[2][4][4];
    #pragma unroll
    for (int a = 0; a < 2; a++)
        #pragma unroll
        for (int b = 0; b < 4; b++)
            #pragma unroll
            for (int c = 0; c < 4; c++) acc[a][b][c] = 0.f;

    mm_mainloop<NN / 32>(g_attn + (size_t)z * NN * NN + (size_t)i0 * NN, NN,
                         g_hpT + (size_t)z * FOUT * NN + (size_t)o0 * NN, NN, acc);

    const int b  = z & (BSZ - 1);
    const int hd = z >> 2;
    float* obase = out + ((size_t)(b * NH + hd) * NN + i0) * FOUT + o0;
    float* stage = dsm;
    const int tid = threadIdx.x;

    frag_to_stage(stage, acc);
    __syncthreads();
    #pragma unroll
    for (int it = 0; it < 32; it++) {
        int idx = tid + it * 512;               // 128 rows x 128 cols
        int c   = idx & 127;
        int r_l = idx >> 7;
        obase[(size_t)r_l * FOUT + c] = stage[r_l * 129 + c] + __ldg(bias + o0 + c);
    }
}

// ---------------- h -> tf32-rounded copy ----------------
__global__ void hR_kernel(const float* __restrict__ h)
{
    size_t i = ((size_t)blockIdx.x * 256 + threadIdx.x) * 4;
    float4 v = *(const float4*)(h + i);
    float4 o;
    o.x = f2tf_f(v.x); o.y = f2tf_f(v.y); o.z = f2tf_f(v.z); o.w = f2tf_f(v.w);
    *(float4*)(g_hR + i) = o;
}

// ---------------- w transpose + tf32 round ----------------
__global__ void wT_kernel(const float* __restrict__ w)
{
    __shared__ float t[32][33];
    const int hd = blockIdx.z;
    const int f0 = blockIdx.y * 32, o0 = blockIdx.x * 32;
    const int x = threadIdx.x, y = threadIdx.y;   // 32 x 8
    const float* src = w + (size_t)hd * FIN * FOUT;
    #pragma unroll
    for (int i = 0; i < 32; i += 8)
        t[y + i][x] = src[(size_t)(f0 + y + i) * FOUT + o0 + x];
    __syncthreads();
    float* dst = g_wT + (size_t)hd * FOUT * FIN;
    #pragma unroll
    for (int i = 0; i < 32; i += 8)
        dst[(size_t)(o0 + y + i) * FIN + f0 + x] = f2tf_f(t[x][y + i]);
}

// ---------------- adj dtype detection (parallel) ----------------
__global__ void adj_zero_kernel() { g_n01 = 0; g_nf = 0; }

__global__ void adj_detect_kernel(const uint32_t* __restrict__ adj_words)
{
    __shared__ int s1, s2;
    if (threadIdx.x == 0) { s1 = 0; s2 = 0; }
    __syncthreads();
    int n01 = 0, nf = 0;
    const int NWORDS = 1 << 20;
    for (int i = blockIdx.x * blockDim.x + threadIdx.x; i < NWORDS;
         i += gridDim.x * blockDim.x) {
        uint32_t v = adj_words[i];
        n01 |= (v > 1u);
        nf  |= (v != 0u && v != 0x3f800000u);
    }
    if (n01) atomicOr(&s1, 1);
    if (nf)  atomicOr(&s2, 1);
    __syncthreads();
    if (threadIdx.x == 0) {
        if (s1) atomicOr(&g_n01, 1);
        if (s2) atomicOr(&g_nf, 1);
    }
}

__global__ void adj_final_kernel() {
    g_adjmode = (!g_n01) ? 0 : ((!g_nf) ? 1 : 2);
}

// ---------------- attn_src/dst: 4-way o-split, SMEM reduce ----------------
__global__ __launch_bounds__(256) void attvec_kernel(
    const float* __restrict__ a_src, const float* __restrict__ a_dst)
{
    __shared__ float sa[FOUT], sd[FOUT];
    __shared__ float p1[4][64], p2[4][64];
    const int z  = blockIdx.y;
    const int hd = z >> 2;
    for (int o = threadIdx.x; o < FOUT; o += 256) {
        sa[o] = a_src[hd * FOUT + o];
        sd[o] = a_dst[hd * FOUT + o];
    }
    __syncthreads();

    const int n_l = threadIdx.x & 63;
    const int oc  = threadIdx.x >> 6;
    const int n   = blockIdx.x * 64 + n_l;
    const float* col = g_hpT + (size_t)z * FOUT * NN + n;

    float s1 = 0.f, s2 = 0.f;
    const int obeg = oc * 192;
    #pragma unroll 4
    for (int o = obeg; o < obeg + 192; o++) {
        float t = tanhf(col[(size_t)o * NN]);
        s1 += t * sa[o];
        s2 += t * sd[o];
    }
    p1[oc][n_l] = s1;
    p2[oc][n_l] = s2;
    __syncthreads();

    if (threadIdx.x < 64) {
        int t = threadIdx.x;
        g_src[z * NN + blockIdx.x * 64 + t] = p1[0][t] + p1[1][t] + p1[2][t] + p1[3][t];
    } else if (threadIdx.x < 128) {
        int t = threadIdx.x - 64;
        g_dst[z * NN + blockIdx.x * 64 + t] = p2[0][t] + p2[1][t] + p2[2][t] + p2[3][t];
    }
}

// ---------------- masked softmax (register-resident; writes tf32-rounded attn) ----------------
__global__ __launch_bounds__(256) void softmax_kernel(const void* __restrict__ adj)
{
    __shared__ float sdst[NN];
    __shared__ float redm[8], reds[8], bcast[2];

    const int z = blockIdx.y;
    const int i = blockIdx.x;
    const int b = z & (BSZ - 1);
    const int tid = threadIdx.x, lane = tid & 31, wid = tid >> 5;

    const float* dstrow = g_dst + (size_t)z * NN;
    for (int j = tid * 4; j < NN; j += 256 * 4)
        *(float4*)&sdst[j] = *(const float4*)&dstrow[j];
    __syncthreads();

    const float srcv = g_src[(size_t)z * NN + i];
    const size_t rowbase = ((size_t)b * NN + i) * NN;
    const int j0 = tid * 8;

    uint32_t keep8 = 0;
    const int mode = g_adjmode;
    if (mode == 0) {
        const int* arow = (const int*)adj + rowbase;
        int4 w0 = *(const int4*)(arow + j0);
        int4 w1 = *(const int4*)(arow + j0 + 4);
        keep8 = (w0.x != 0) | ((w0.y != 0) << 1) | ((w0.z != 0) << 2) | ((w0.w != 0) << 3)
              | ((w1.x != 0) << 4) | ((w1.y != 0) << 5) | ((w1.z != 0) << 6) | ((w1.w != 0) << 7);
    } else if (mode == 1) {
        const float* arow = (const float*)adj + rowbase;
        float4 w0 = *(const float4*)(arow + j0);
        float4 w1 = *(const float4*)(arow + j0 + 4);
        keep8 = (w0.x != 0.f) | ((w0.y != 0.f) << 1) | ((w0.z != 0.f) << 2) | ((w0.w != 0.f) << 3)
              | ((w1.x != 0.f) << 4) | ((w1.y != 0.f) << 5) | ((w1.z != 0.f) << 6) | ((w1.w != 0.f) << 7);
    } else {
        const uint8_t* arow = (const uint8_t*)adj + rowbase;
        uint2 mraw = *(const uint2*)(arow + j0);
        #pragma unroll
        for (int u = 0; u < 4; u++) {
            keep8 |= (((mraw.x >> (8 * u)) & 0xffu) != 0u) << u;
            keep8 |= (((mraw.y >> (8 * u)) & 0xffu) != 0u) << (u + 4);
        }
    }

    float v[8];
    float mx = NEG_INF;
    #pragma unroll
    for (int u = 0; u < 8; u++) {
        int j = j0 + u;
        bool keep = ((keep8 >> u) & 1u) || (j == i);
        float s = srcv + sdst[j];
        s = (s >= 0.f) ? s : NEG_SLOPE * s;
        v[u] = keep ? s : NEG_INF;
        mx = fmaxf(mx, v[u]);
    }

    #pragma unroll
    for (int off = 16; off; off >>= 1) mx = fmaxf(mx, __shfl_xor_sync(0xffffffffu, mx, off));
    if (lane == 0) redm[wid] = mx;
    __syncthreads();
    if (tid < 8) {
        float x = redm[tid];
        #pragma unroll
        for (int off = 4; off; off >>= 1) x = fmaxf(x, __shfl_xor_sync(0xffu, x, off));
        if (tid == 0) bcast[0] = x;
    }
    __syncthreads();
    const float smax = bcast[0];

    float lsum = 0.f;
    #pragma unroll
    for (int u = 0; u < 8; u++) {
        float e = (v[u] == NEG_INF) ? 0.f : __expf(v[u] - smax);
        v[u] = e;
        lsum += e;
    }
    #pragma unroll
    for (int off = 16; off; off >>= 1) lsum += __shfl_xor_sync(0xffffffffu, lsum, off);
    if (lane == 0) reds[wid] = lsum;
    __syncthreads();
    if (tid < 8) {
        float x = reds[tid];
        #pragma unroll
        for (int off = 4; off; off >>= 1) x += __shfl_xor_sync(0xffu, x, off);
        if (tid == 0) bcast[1] = 1.f / x;
    }
    __syncthreads();
    const float inv = bcast[1];

    float* outrow = g_attn + ((size_t)z * NN + i) * NN;
    #pragma unroll
    for (int u = 0; u < 8; u += 4) {
        float4 o4;
        o4.x = f2tf_f(v[u + 0] * inv); o4.y = f2tf_f(v[u + 1] * inv);
        o4.z = f2tf_f(v[u + 2] * inv); o4.w = f2tf_f(v[u + 3] * inv);
        *(float4*)(outrow + j0 + u) = o4;
    }
}

// ---------------- launch ----------------
extern "C" void kernel_launch(void* const* d_in, const int* in_sizes, int n_in,
                              void* d_out, int out_size)
{
    const float *h = nullptr, *w = nullptr, *a_src = nullptr, *a_dst = nullptr, *bias = nullptr;
    const void  *adj = nullptr;
    for (int k = 0; k < n_in; k++) {
        switch (in_sizes[k]) {
            case BSZ * NN * FIN:  h   = (const float*)d_in[k]; break;
            case BSZ * NN * NN:   adj = d_in[k];               break;
            case NH * FIN * FOUT: w   = (const float*)d_in[k]; break;
            case NH * FOUT:       if (!a_src) a_src = (const float*)d_in[k];
                                  else        a_dst = (const float*)d_in[k]; break;
            case FOUT:            bias = (const float*)d_in[k]; break;
            default: break;
        }
    }
    float* out = (float*)d_out;

    cudaFuncSetAttribute(gemm1_tc, cudaFuncAttributeMaxDynamicSharedMemorySize, DSM_BYTES);
    cudaFuncSetAttribute(gemm2_tc, cudaFuncAttributeMaxDynamicSharedMemorySize, DSM_BYTES);

    adj_zero_kernel<<<1, 1>>>();
    adj_detect_kernel<<<64, 256>>>((const uint32_t*)adj);
    adj_final_kernel<<<1, 1>>>();

    hR_kernel<<<(BSZ * NN * FIN) / (256 * 4), 256>>>(h);

    dim3 gw(FOUT / 32, FIN / 32, NH);
    wT_kernel<<<gw, dim3(32, 8)>>>(w);

    dim3 g1(FOUT / 128, (BSZ * NN) / 128, NH);            // (6, 64, 2)
    gemm1_tc<<<g1, 512, DSM_BYTES>>>();

    attvec_kernel<<<dim3(NN / 64, NH * BSZ), 256>>>(a_src, a_dst);

    softmax_kernel<<<dim3(NN, NH * BSZ), 256>>>(adj);

    dim3 g2(FOUT / 128, NN / 128, NH * BSZ);              // (6, 16, 8)
    gemm2_tc<<<g2, 512, DSM_BYTES>>>(bias, out);
}